// round 15
// baseline (speedup 1.0000x reference)
#include <cuda_runtime.h>
#include <cstdint>
#include <cstddef>

#define T_STEPS 2048
#define BATCH   64
#define IDIM    512
#define HDIM    512
#define GDIM    2048                 // 4*H, gate order [f|i|o|c]
#define BH      (BATCH * HDIM)       // 32768
#define NCTA_REC 128

// 1 GiB scratch for precomputed input-side gates Xg[t, b, 4H] (fp32, bias folded in)
__device__ float g_Xg[(size_t)T_STEPS * BATCH * GDIM];
// h exchange buffers in exact tf32 B-fragment layout: [parity][group][8192 words]
__device__ unsigned g_hfrag[2][4][8192];
// per-CTA arrival flags, 128B-strided: [group][jt][pad]
__device__ unsigned g_flags[4][32][32];

__device__ __forceinline__ unsigned f2tf32(float x) {
    unsigned r;
    asm("cvt.rna.tf32.f32 %0, %1;" : "=r"(r) : "f"(x));
    return r;
}
__device__ __forceinline__ float tanh_f(float x) {
    float y;
    asm("tanh.approx.f32 %0, %1;" : "=f"(y) : "f"(x));
    return y;
}
__device__ __forceinline__ unsigned ld_acq(const unsigned* p) {
    unsigned v;
    asm volatile("ld.global.acquire.gpu.u32 %0, [%1];" : "=r"(v) : "l"(p) : "memory");
    return v;
}
__device__ __forceinline__ void st_rel(unsigned* p, unsigned v) {
    asm volatile("st.global.release.gpu.u32 [%0], %1;" :: "l"(p), "r"(v) : "memory");
}
__device__ __forceinline__ void cp16(void* dst_smem, const void* src) {
    unsigned d = (unsigned)__cvta_generic_to_shared(dst_smem);
    asm volatile("cp.async.ca.shared.global [%0], [%1], 16;" :: "r"(d), "l"(src));
}
__device__ __forceinline__ void cp_commit() {
    asm volatile("cp.async.commit_group;");
}
__device__ __forceinline__ void cp_wait0() {
    asm volatile("cp.async.wait_group 0;");
}
__device__ __forceinline__ void cp_wait1() {
    asm volatile("cp.async.wait_group 1;");
}
// ldmatrix x4: loads four 8x8 b16 matrices == one 16x8 tf32 A-fragment set
#define LDSM_X4(r0, r1, r2, r3, addr) \
    asm volatile("ldmatrix.sync.aligned.m8n8.x4.shared.b16 {%0,%1,%2,%3}, [%4];" \
                 : "=r"(r0), "=r"(r1), "=r"(r2), "=r"(r3) : "r"(addr))

__device__ __forceinline__ void mma_tf32(float &d0, float &d1, float &d2, float &d3,
                                         unsigned a0, unsigned a1, unsigned a2, unsigned a3,
                                         unsigned b0, unsigned b1) {
    asm volatile(
        "mma.sync.aligned.m16n8k8.row.col.f32.tf32.tf32.f32 "
        "{%0,%1,%2,%3}, {%4,%5,%6,%7}, {%8,%9}, {%0,%1,%2,%3};\n"
        : "+f"(d0), "+f"(d1), "+f"(d2), "+f"(d3)
        : "r"(a0), "r"(a1), "r"(a2), "r"(a3), "r"(b0), "r"(b1));
}

// ===========================================================================
// Phase 1: Xg = X @ Wx + b  ([131072 x 512] @ [512 x 2048])
// CTA tile 128x256, cp.async double-buffered, A frags via ldmatrix.x4.
// (unchanged — R14 best)
// ===========================================================================
#define XA_STRIDE 36
#define XB_STRIDE 264
#define XA_WORDS (128 * XA_STRIDE)          // 4608
#define XB_WORDS (32 * XB_STRIDE)           // 8448
#define XBUF_WORDS (XA_WORDS + XB_WORDS)    // 13056
#define XG_SMEM (2 * XBUF_WORDS * 4)        // 104448 B

__device__ __forceinline__ void xg_issue(const float* __restrict__ X,
                                         const float* __restrict__ Wx,
                                         int m0, int col0, int k0, int tid,
                                         float* As, float* Bs)
{
    #pragma unroll
    for (int i = 0; i < 4; i++) {
        int idx = tid + i * 256;                 // 1024 float4 slots (A: 128x32)
        int r = idx >> 3;
        int c4 = (idx & 7) * 4;
        cp16(As + r * XA_STRIDE + c4, X + (size_t)(m0 + r) * IDIM + k0 + c4);
    }
    #pragma unroll
    for (int i = 0; i < 8; i++) {
        int idx = tid + i * 256;                 // 2048 float4 slots (B: 32x256)
        int kr = idx >> 6;
        int nf = (idx & 63) * 4;
        cp16(Bs + kr * XB_STRIDE + nf, Wx + (size_t)(k0 + kr) * HDIM + col0 + nf);
    }
}

__global__ void __launch_bounds__(256, 1) xgemm_kernel(
    const float* __restrict__ X,
    const float* __restrict__ Wxf, const float* __restrict__ Wxi,
    const float* __restrict__ Wxo, const float* __restrict__ Wxc,
    const float* __restrict__ bf, const float* __restrict__ bi,
    const float* __restrict__ bo, const float* __restrict__ bc)
{
    extern __shared__ float xsm[];

    const int tid  = threadIdx.x;
    const int warp = tid >> 5;
    const int lane = tid & 31;
    const int m0 = blockIdx.y * 128;
    const int n0 = blockIdx.x * 256;
    const int wm = (warp >> 2) * 64;    // warp grid 2(M) x 4(N); warp tile 64x64
    const int wn = (warp & 3) * 64;

    if (blockIdx.x == 0 && blockIdx.y == 0) {
        unsigned* f = reinterpret_cast<unsigned*>(g_flags);
        for (int i = tid; i < 4 * 32 * 32; i += 256) f[i] = 0u;
    }

    const int g    = n0 >> 9;           // 256-wide slab lies in one gate
    const int col0 = n0 & 511;
    const float* Wx = (g == 0) ? Wxf : (g == 1) ? Wxi : (g == 2) ? Wxo : Wxc;
    const float* bb = (g == 0) ? bf  : (g == 1) ? bi  : (g == 2) ? bo  : bc;

    const unsigned xsm_base = (unsigned)__cvta_generic_to_shared(xsm);
    const int a_mrow  = wm + ((lane >> 3) & 1) * 8 + (lane & 7);
    const int a_khalf = (lane >> 4) * 4;

    float acc[4][8][4];
    #pragma unroll
    for (int mt = 0; mt < 4; mt++)
        #pragma unroll
        for (int nt = 0; nt < 8; nt++)
            #pragma unroll
            for (int e = 0; e < 4; e++) acc[mt][nt][e] = 0.f;

    xg_issue(X, Wx, m0, col0, 0, tid, xsm, xsm + XA_WORDS);
    cp_commit();

    #pragma unroll 1
    for (int kc = 0; kc < 16; kc++) {
        if (kc < 15) {
            float* nb = xsm + ((kc + 1) & 1) * XBUF_WORDS;
            xg_issue(X, Wx, m0, col0, (kc + 1) * 32, tid, nb, nb + XA_WORDS);
            cp_commit();
            cp_wait1();
        } else {
            cp_wait0();
        }
        __syncthreads();

        const unsigned abuf = xsm_base + ((kc & 1) * XBUF_WORDS) * 4;
        const unsigned a_lane_addr = abuf + (unsigned)(a_mrow * XA_STRIDE + a_khalf) * 4;
        const unsigned* Bu = reinterpret_cast<const unsigned*>(xsm + (kc & 1) * XBUF_WORDS) + XA_WORDS;

        #pragma unroll
        for (int kk = 0; kk < 32; kk += 8) {
            unsigned a[4][4], b[8][2];
            const int kcol = kk + (lane & 3);
            #pragma unroll
            for (int mt = 0; mt < 4; mt++) {
                LDSM_X4(a[mt][0], a[mt][1], a[mt][2], a[mt][3],
                        a_lane_addr + (unsigned)(mt * 16 * XA_STRIDE + kk) * 4);
            }
            #pragma unroll
            for (int nt = 0; nt < 8; nt++) {
                int n = wn + nt * 8 + (lane >> 2);
                b[nt][0] = Bu[kcol * XB_STRIDE + n];
                b[nt][1] = Bu[(kcol + 4) * XB_STRIDE + n];
            }
            #pragma unroll
            for (int mt = 0; mt < 4; mt++)
                #pragma unroll
                for (int nt = 0; nt < 8; nt++)
                    mma_tf32(acc[mt][nt][0], acc[mt][nt][1], acc[mt][nt][2], acc[mt][nt][3],
                             a[mt][0], a[mt][1], a[mt][2], a[mt][3],
                             b[nt][0], b[nt][1]);
        }
        __syncthreads();
    }

    #pragma unroll
    for (int mt = 0; mt < 4; mt++) {
        #pragma unroll
        for (int nt = 0; nt < 8; nt++) {
            int nloc = wn + nt * 8 + (lane & 3) * 2;
            int r = m0 + wm + mt * 16 + (lane >> 2);
            float bv0 = bb[col0 + nloc];
            float bv1 = bb[col0 + nloc + 1];
            float2 v0 = make_float2(acc[mt][nt][0] + bv0, acc[mt][nt][1] + bv1);
            float2 v1 = make_float2(acc[mt][nt][2] + bv0, acc[mt][nt][3] + bv1);
            *reinterpret_cast<float2*>(&g_Xg[(size_t)r * GDIM + n0 + nloc]) = v0;
            *reinterpret_cast<float2*>(&g_Xg[(size_t)(r + 8) * GDIM + n0 + nloc]) = v1;
        }
    }
}

// ===========================================================================
// Phase 2: persistent recurrence — R11 protocol, R15 work split:
// 512 threads = 16 warps = 2 M-tiles x 8 K-splits (K=64 each).
// Halves the serial ki chain (8 vs 16) and LDG pipeline depth (4+4 vs 8+8);
// per-thread W state 64 regs -> fits the 128-reg cap at 512 threads.
// Exchange protocol byte-identical to R11 (best measured).
// ===========================================================================
#define REC_THREADS 512
#define GS2_WORDS (8 * 64 * 18)                       // [ks][gatecol][batch pad18]
#define REC_SMEM (GS2_WORDS * 4 + 1024)               // gs2 + pub

__global__ void __launch_bounds__(512, 1) lstm_rec_kernel(
    float* __restrict__ out,
    const float* __restrict__ Whf, const float* __restrict__ Whi,
    const float* __restrict__ Who, const float* __restrict__ Whc)
{
    extern __shared__ unsigned char smem_raw[];
    float* gs2 = reinterpret_cast<float*>(smem_raw);                       // [8][64][18]
    unsigned* pub = reinterpret_cast<unsigned*>(smem_raw + GS2_WORDS * 4); // 256 words

    const int tid  = threadIdx.x;
    const int warp = tid >> 5;
    const int lane = tid & 31;
    const int bt = blockIdx.x >> 5;   // batch group 0..3 (16 rows)
    const int jt = blockIdx.x & 31;   // hidden tile 0..31 (16 cols)

    const int mt = warp >> 3;         // M half: gates {f,i} (0) or {o,c} (1)
    const int ks = warp & 7;          // K chunk 0..7 (64 each)

    // ---- one-time: W_h A-fragments into registers (2 tiles x 8 ki x 4) ----
    unsigned Wr0[8][4], Wr1[8][4];
    {
        const float* Wh0 = (mt == 0) ? Whf : Who;   // tile 0 -> gate mt*2
        const float* Wh1 = (mt == 0) ? Whi : Whc;   // tile 1 -> gate mt*2+1
        const int colA = jt * 16 + (lane >> 2);
        #pragma unroll
        for (int ki = 0; ki < 8; ki++) {
            int k = ks * 64 + ki * 8 + (lane & 3);
            Wr0[ki][0] = f2tf32(Wh0[(size_t)k * HDIM + colA]);
            Wr0[ki][1] = f2tf32(Wh0[(size_t)k * HDIM + colA + 8]);
            Wr0[ki][2] = f2tf32(Wh0[(size_t)(k + 4) * HDIM + colA]);
            Wr0[ki][3] = f2tf32(Wh0[(size_t)(k + 4) * HDIM + colA + 8]);
            Wr1[ki][0] = f2tf32(Wh1[(size_t)k * HDIM + colA]);
            Wr1[ki][1] = f2tf32(Wh1[(size_t)k * HDIM + colA + 8]);
            Wr1[ki][2] = f2tf32(Wh1[(size_t)(k + 4) * HDIM + colA]);
            Wr1[ki][3] = f2tf32(Wh1[(size_t)(k + 4) * HDIM + colA + 8]);
        }
    }

    // cell thread mapping (tid < 256): owns c[bt*16+eb][jt*16+ej]
    const int eb = tid >> 4;
    const int ej = tid & 15;
    float c_val = 0.f;

    // position of h[eb][ej] within CTA's contiguous 1KB B-frag block
    const int lidx = ((ej >> 3) << 7) + (((eb & 7) << 2) + (ej & 3)) * 4
                     + ((eb >> 3) << 1) + ((ej >> 2) & 1);

    // Xg prefetch for t=0 (tid < 256)
    float xgv[4] = {0.f, 0.f, 0.f, 0.f};
    if (tid < 256) {
        size_t xb = ((size_t)bt * 16 + eb) * GDIM + jt * 16 + ej;
        #pragma unroll
        for (int g = 0; g < 4; g++) xgv[g] = g_Xg[xb + g * HDIM];
    }
    __syncthreads();

    #pragma unroll 1
    for (int t = 0; t < T_STEPS; t++) {
        // ---- recurrent mma: pipelined LDG (depth 4) + register W, 8 ki ----
        float A00[4] = {0.f,0.f,0.f,0.f}, A01[4] = {0.f,0.f,0.f,0.f};
        float A10[4] = {0.f,0.f,0.f,0.f}, A11[4] = {0.f,0.f,0.f,0.f};
        if (t > 0) {
            const uint4* hp = reinterpret_cast<const uint4*>(g_hfrag[(t - 1) & 1][bt])
                              + ks * 256 + lane;
            uint4 hbuf[4];
            #pragma unroll
            for (int i = 0; i < 4; i++)
                hbuf[i] = __ldcg(hp + i * 32);
            #pragma unroll
            for (int ki = 0; ki < 8; ki++) {
                uint4 hb = hbuf[ki & 3];
                if (ki < 4)
                    hbuf[ki & 3] = __ldcg(hp + (ki + 4) * 32);   // refill under mma
                mma_tf32(A00[0], A00[1], A00[2], A00[3],
                         Wr0[ki][0], Wr0[ki][1], Wr0[ki][2], Wr0[ki][3], hb.x, hb.y);
                mma_tf32(A01[0], A01[1], A01[2], A01[3],
                         Wr0[ki][0], Wr0[ki][1], Wr0[ki][2], Wr0[ki][3], hb.z, hb.w);
                mma_tf32(A10[0], A10[1], A10[2], A10[3],
                         Wr1[ki][0], Wr1[ki][1], Wr1[ki][2], Wr1[ki][3], hb.x, hb.y);
                mma_tf32(A11[0], A11[1], A11[2], A11[3],
                         Wr1[ki][0], Wr1[ki][1], Wr1[ki][2], Wr1[ki][3], hb.z, hb.w);
            }
        }

        // ---- K-partials to smem: [ks][gatecol][batch] ----
        {
            const int r  = lane >> 2;
            const int c2 = (lane & 3) * 2;
            float* g0 = gs2 + (ks * 64 + mt * 32) * 18;        // tile 0 cols
            float* g1 = g0 + 16 * 18;                          // tile 1 cols
            *reinterpret_cast<float2*>(&g0[r * 18 + c2])           = make_float2(A00[0], A00[1]);
            *reinterpret_cast<float2*>(&g0[(r + 8) * 18 + c2])     = make_float2(A00[2], A00[3]);
            *reinterpret_cast<float2*>(&g0[r * 18 + 8 + c2])       = make_float2(A01[0], A01[1]);
            *reinterpret_cast<float2*>(&g0[(r + 8) * 18 + 8 + c2]) = make_float2(A01[2], A01[3]);
            *reinterpret_cast<float2*>(&g1[r * 18 + c2])           = make_float2(A10[0], A10[1]);
            *reinterpret_cast<float2*>(&g1[(r + 8) * 18 + c2])     = make_float2(A10[2], A10[3]);
            *reinterpret_cast<float2*>(&g1[r * 18 + 8 + c2])       = make_float2(A11[0], A11[1]);
            *reinterpret_cast<float2*>(&g1[(r + 8) * 18 + 8 + c2]) = make_float2(A11[2], A11[3]);
        }
        __syncthreads();

        // ---- cell (tid < 256): reduce 8 K-partials per gate + LSTM ----
        float hv = 0.f;
        if (tid < 256) {
            float gate[4];
            #pragma unroll
            for (int g = 0; g < 4; g++) {
                float s = xgv[g];
                #pragma unroll
                for (int k = 0; k < 8; k++)
                    s += gs2[(k * 64 + g * 16 + ej) * 18 + eb];
                gate[g] = s;
            }
            float fg = 0.5f * tanh_f(0.5f * gate[0]) + 0.5f;
            float ig = 0.5f * tanh_f(0.5f * gate[1]) + 0.5f;
            float og = 0.5f * tanh_f(0.5f * gate[2]) + 0.5f;
            float ch = tanh_f(gate[3]);
            c_val = fg * c_val + ig * ch;
            hv = og * tanh_f(c_val);
            pub[lidx] = f2tf32(hv);
        }
        __syncthreads();     // pub ready; also protects gs2 WAR for next step

        // ---- warp0 publishes contiguous 1KB + releases flag ----
        if (warp == 0) {
            uint4* dst = reinterpret_cast<uint4*>(&g_hfrag[t & 1][bt][jt * 256]);
            const uint4* ps = reinterpret_cast<const uint4*>(pub);
            dst[lane]      = ps[lane];
            dst[lane + 32] = ps[lane + 32];
            __syncwarp();
            if (lane == 0 && t + 1 < T_STEPS) {
                st_rel(&g_flags[bt][jt][0], (unsigned)(t + 1));
            }
        }

        // ---- off-critical-path output + next-step Xg prefetch (tid<256) ----
        if (tid < 256) {
            size_t oidx = (size_t)t * BH + (size_t)(bt * 16 + eb) * HDIM + (size_t)jt * 16 + ej;
            out[oidx] = hv;
            if (t == T_STEPS - 1) {
                size_t tail = (size_t)T_STEPS * BH + (size_t)(bt * 16 + eb) * HDIM + (size_t)jt * 16 + ej;
                out[tail]      = hv;      // h_T
                out[tail + BH] = c_val;   // c_T
            }
            if (t + 1 < T_STEPS) {
                size_t xb = ((size_t)(t + 1) * BATCH + (size_t)bt * 16 + eb) * GDIM + jt * 16 + ej;
                #pragma unroll
                for (int g = 0; g < 4; g++) xgv[g] = g_Xg[xb + g * HDIM];
            }
        }

        // ---- group barrier (32 CTAs of this batch group), polled by warp1 ----
        if (t + 1 < T_STEPS) {
            if (warp == 1) {
                const unsigned* fp = &g_flags[bt][lane][0];
                while (ld_acq(fp) < (unsigned)(t + 1)) { }
            }
            __syncthreads();
        }
    }
}

// ===========================================================================
extern "C" void kernel_launch(void* const* d_in, const int* in_sizes, int n_in,
                              void* d_out, int out_size)
{
    const float* X   = (const float*)d_in[0];
    const float* Wxf = (const float*)d_in[1];
    const float* Whf = (const float*)d_in[2];
    const float* bf  = (const float*)d_in[3];
    const float* Wxi = (const float*)d_in[4];
    const float* Whi = (const float*)d_in[5];
    const float* bi  = (const float*)d_in[6];
    const float* Wxo = (const float*)d_in[7];
    const float* Who = (const float*)d_in[8];
    const float* bo  = (const float*)d_in[9];
    const float* Wxc = (const float*)d_in[10];
    const float* Whc = (const float*)d_in[11];
    const float* bc  = (const float*)d_in[12];
    float* out = (float*)d_out;

    cudaFuncSetAttribute(xgemm_kernel,
                         cudaFuncAttributeMaxDynamicSharedMemorySize, XG_SMEM);
    cudaFuncSetAttribute(lstm_rec_kernel,
                         cudaFuncAttributeMaxDynamicSharedMemorySize, REC_SMEM);

    dim3 grid1(GDIM / 256, (T_STEPS * BATCH) / 128);
    xgemm_kernel<<<grid1, 256, XG_SMEM>>>(X, Wxf, Wxi, Wxo, Wxc, bf, bi, bo, bc);
    lstm_rec_kernel<<<NCTA_REC, REC_THREADS, REC_SMEM>>>(out, Whf, Whi, Who, Whc);
}

// round 16
// speedup vs baseline: 1.0232x; 1.0232x over previous
#include <cuda_runtime.h>
#include <cstdint>
#include <cstddef>

#define T_STEPS 2048
#define BATCH   64
#define IDIM    512
#define HDIM    512
#define GDIM    2048                 // 4*H, gate order [f|i|o|c]
#define BH      (BATCH * HDIM)       // 32768
#define NCTA_REC 128

// 1 GiB scratch for precomputed input-side gates Xg[t, b, 4H] (fp32, bias folded in)
__device__ float g_Xg[(size_t)T_STEPS * BATCH * GDIM];
// h exchange buffers in exact tf32 B-fragment layout: [parity][group][8192 words]
__device__ unsigned g_hfrag[2][4][8192];
// per-CTA arrival flags, 128B-strided: [group][jt][pad]
__device__ unsigned g_flags[4][32][32];

__device__ __forceinline__ unsigned f2tf32(float x) {
    unsigned r;
    asm("cvt.rna.tf32.f32 %0, %1;" : "=r"(r) : "f"(x));
    return r;
}
__device__ __forceinline__ float tanh_f(float x) {
    float y;
    asm("tanh.approx.f32 %0, %1;" : "=f"(y) : "f"(x));
    return y;
}
__device__ __forceinline__ unsigned ld_acq(const unsigned* p) {
    unsigned v;
    asm volatile("ld.global.acquire.gpu.u32 %0, [%1];" : "=r"(v) : "l"(p) : "memory");
    return v;
}
__device__ __forceinline__ void st_rel(unsigned* p, unsigned v) {
    asm volatile("st.global.release.gpu.u32 [%0], %1;" :: "l"(p), "r"(v) : "memory");
}
__device__ __forceinline__ void cp16(void* dst_smem, const void* src) {
    unsigned d = (unsigned)__cvta_generic_to_shared(dst_smem);
    asm volatile("cp.async.ca.shared.global [%0], [%1], 16;" :: "r"(d), "l"(src));
}
__device__ __forceinline__ void cp_commit() {
    asm volatile("cp.async.commit_group;");
}
__device__ __forceinline__ void cp_wait0() {
    asm volatile("cp.async.wait_group 0;");
}
__device__ __forceinline__ void cp_wait1() {
    asm volatile("cp.async.wait_group 1;");
}
__device__ __forceinline__ void cp_wait2() {
    asm volatile("cp.async.wait_group 2;");
}
// ldmatrix x4: loads four 8x8 b16 matrices == one 16x8 tf32 A-fragment set
#define LDSM_X4(r0, r1, r2, r3, addr) \
    asm volatile("ldmatrix.sync.aligned.m8n8.x4.shared.b16 {%0,%1,%2,%3}, [%4];" \
                 : "=r"(r0), "=r"(r1), "=r"(r2), "=r"(r3) : "r"(addr))

__device__ __forceinline__ void mma_tf32(float &d0, float &d1, float &d2, float &d3,
                                         unsigned a0, unsigned a1, unsigned a2, unsigned a3,
                                         unsigned b0, unsigned b1) {
    asm volatile(
        "mma.sync.aligned.m16n8k8.row.col.f32.tf32.tf32.f32 "
        "{%0,%1,%2,%3}, {%4,%5,%6,%7}, {%8,%9}, {%0,%1,%2,%3};\n"
        : "+f"(d0), "+f"(d1), "+f"(d2), "+f"(d3)
        : "r"(a0), "r"(a1), "r"(a2), "r"(a3), "r"(b0), "r"(b1));
}

// ===========================================================================
// Phase 1: Xg = X @ Wx + b  ([131072 x 512] @ [512 x 2048])
// CTA tile 128x256; R16: 3-STAGE cp.async pipeline (prefetch distance 2)
// to cover the per-chunk DRAM/L2 fill latency that depth-2 exposed.
// ===========================================================================
#define XA_STRIDE 36
#define XB_STRIDE 264
#define XA_WORDS (128 * XA_STRIDE)          // 4608
#define XB_WORDS (32 * XB_STRIDE)           // 8448
#define XBUF_WORDS (XA_WORDS + XB_WORDS)    // 13056
#define XG_STAGES 3
#define XG_SMEM (XG_STAGES * XBUF_WORDS * 4)   // 156672 B

__device__ __forceinline__ void xg_issue(const float* __restrict__ X,
                                         const float* __restrict__ Wx,
                                         int m0, int col0, int k0, int tid,
                                         float* As, float* Bs)
{
    #pragma unroll
    for (int i = 0; i < 4; i++) {
        int idx = tid + i * 256;                 // 1024 float4 slots (A: 128x32)
        int r = idx >> 3;
        int c4 = (idx & 7) * 4;
        cp16(As + r * XA_STRIDE + c4, X + (size_t)(m0 + r) * IDIM + k0 + c4);
    }
    #pragma unroll
    for (int i = 0; i < 8; i++) {
        int idx = tid + i * 256;                 // 2048 float4 slots (B: 32x256)
        int kr = idx >> 6;
        int nf = (idx & 63) * 4;
        cp16(Bs + kr * XB_STRIDE + nf, Wx + (size_t)(k0 + kr) * HDIM + col0 + nf);
    }
}

__global__ void __launch_bounds__(256, 1) xgemm_kernel(
    const float* __restrict__ X,
    const float* __restrict__ Wxf, const float* __restrict__ Wxi,
    const float* __restrict__ Wxo, const float* __restrict__ Wxc,
    const float* __restrict__ bf, const float* __restrict__ bi,
    const float* __restrict__ bo, const float* __restrict__ bc)
{
    extern __shared__ float xsm[];

    const int tid  = threadIdx.x;
    const int warp = tid >> 5;
    const int lane = tid & 31;
    const int m0 = blockIdx.y * 128;
    const int n0 = blockIdx.x * 256;
    const int wm = (warp >> 2) * 64;    // warp grid 2(M) x 4(N); warp tile 64x64
    const int wn = (warp & 3) * 64;

    if (blockIdx.x == 0 && blockIdx.y == 0) {
        unsigned* f = reinterpret_cast<unsigned*>(g_flags);
        for (int i = tid; i < 4 * 32 * 32; i += 256) f[i] = 0u;
    }

    const int g    = n0 >> 9;           // 256-wide slab lies in one gate
    const int col0 = n0 & 511;
    const float* Wx = (g == 0) ? Wxf : (g == 1) ? Wxi : (g == 2) ? Wxo : Wxc;
    const float* bb = (g == 0) ? bf  : (g == 1) ? bi  : (g == 2) ? bo  : bc;

    const unsigned xsm_base = (unsigned)__cvta_generic_to_shared(xsm);
    const int a_mrow  = wm + ((lane >> 3) & 1) * 8 + (lane & 7);
    const int a_khalf = (lane >> 4) * 4;

    float acc[4][8][4];
    #pragma unroll
    for (int mt = 0; mt < 4; mt++)
        #pragma unroll
        for (int nt = 0; nt < 8; nt++)
            #pragma unroll
            for (int e = 0; e < 4; e++) acc[mt][nt][e] = 0.f;

    // prologue: chunks 0 and 1 in flight
    xg_issue(X, Wx, m0, col0, 0, tid, xsm, xsm + XA_WORDS);
    cp_commit();
    {
        float* b1 = xsm + XBUF_WORDS;
        xg_issue(X, Wx, m0, col0, 32, tid, b1, b1 + XA_WORDS);
        cp_commit();
    }

    #pragma unroll 1
    for (int kc = 0; kc < 16; kc++) {
        if (kc < 14) {
            float* nb = xsm + ((kc + 2) % XG_STAGES) * XBUF_WORDS;
            xg_issue(X, Wx, m0, col0, (kc + 2) * 32, tid, nb, nb + XA_WORDS);
            cp_commit();
            cp_wait2();                 // chunk kc complete
        } else if (kc == 14) {
            cp_wait1();
        } else {
            cp_wait0();
        }
        __syncthreads();

        const int buf = kc % XG_STAGES;
        const unsigned abuf = xsm_base + (buf * XBUF_WORDS) * 4;
        const unsigned a_lane_addr = abuf + (unsigned)(a_mrow * XA_STRIDE + a_khalf) * 4;
        const unsigned* Bu = reinterpret_cast<const unsigned*>(xsm + buf * XBUF_WORDS) + XA_WORDS;

        #pragma unroll
        for (int kk = 0; kk < 32; kk += 8) {
            unsigned a[4][4], b[8][2];
            const int kcol = kk + (lane & 3);
            #pragma unroll
            for (int mt = 0; mt < 4; mt++) {
                LDSM_X4(a[mt][0], a[mt][1], a[mt][2], a[mt][3],
                        a_lane_addr + (unsigned)(mt * 16 * XA_STRIDE + kk) * 4);
            }
            #pragma unroll
            for (int nt = 0; nt < 8; nt++) {
                int n = wn + nt * 8 + (lane >> 2);
                b[nt][0] = Bu[kcol * XB_STRIDE + n];
                b[nt][1] = Bu[(kcol + 4) * XB_STRIDE + n];
            }
            #pragma unroll
            for (int mt = 0; mt < 4; mt++)
                #pragma unroll
                for (int nt = 0; nt < 8; nt++)
                    mma_tf32(acc[mt][nt][0], acc[mt][nt][1], acc[mt][nt][2], acc[mt][nt][3],
                             a[mt][0], a[mt][1], a[mt][2], a[mt][3],
                             b[nt][0], b[nt][1]);
        }
        __syncthreads();
    }

    #pragma unroll
    for (int mt = 0; mt < 4; mt++) {
        #pragma unroll
        for (int nt = 0; nt < 8; nt++) {
            int nloc = wn + nt * 8 + (lane & 3) * 2;
            int r = m0 + wm + mt * 16 + (lane >> 2);
            float bv0 = bb[col0 + nloc];
            float bv1 = bb[col0 + nloc + 1];
            float2 v0 = make_float2(acc[mt][nt][0] + bv0, acc[mt][nt][1] + bv1);
            float2 v1 = make_float2(acc[mt][nt][2] + bv0, acc[mt][nt][3] + bv1);
            *reinterpret_cast<float2*>(&g_Xg[(size_t)r * GDIM + n0 + nloc]) = v0;
            *reinterpret_cast<float2*>(&g_Xg[(size_t)(r + 8) * GDIM + n0 + nloc]) = v1;
        }
    }
}

// ===========================================================================
// Phase 2: persistent recurrence — R14/R11 configuration VERBATIM (best
// measured: 256 thr = 2 M-tiles x 4 K-splits, pipelined LDG distance-8,
// smem pub staging, warp0 coalesced publish + release, warp1 group poll).
// ===========================================================================
#define REC_THREADS 256
#define GS2_WORDS (4 * 64 * 18)                       // [ks][gatecol][batch pad18]
#define REC_SMEM (GS2_WORDS * 4 + 1024)               // gs2 + pub

__global__ void __launch_bounds__(256, 1) lstm_rec_kernel(
    float* __restrict__ out,
    const float* __restrict__ Whf, const float* __restrict__ Whi,
    const float* __restrict__ Who, const float* __restrict__ Whc)
{
    extern __shared__ unsigned char smem_raw[];
    float* gs2 = reinterpret_cast<float*>(smem_raw);                       // [4][64][18]
    unsigned* pub = reinterpret_cast<unsigned*>(smem_raw + GS2_WORDS * 4); // 256 words

    const int tid  = threadIdx.x;
    const int warp = tid >> 5;
    const int lane = tid & 31;
    const int bt = blockIdx.x >> 5;   // batch group 0..3 (16 rows)
    const int jt = blockIdx.x & 31;   // hidden tile 0..31 (16 cols)

    const int mt = warp >> 2;         // M half: gates {f,i} (0) or {o,c} (1)
    const int ks = warp & 3;          // K chunk 0..3 (128 each)

    // ---- one-time: W_h A-fragments into registers (2 tiles x 16 ki x 4) ----
    unsigned Wr0[16][4], Wr1[16][4];
    {
        const float* Wh0 = (mt == 0) ? Whf : Who;   // tile 0 -> gate mt*2
        const float* Wh1 = (mt == 0) ? Whi : Whc;   // tile 1 -> gate mt*2+1
        const int colA = jt * 16 + (lane >> 2);
        #pragma unroll
        for (int ki = 0; ki < 16; ki++) {
            int k = ks * 128 + ki * 8 + (lane & 3);
            Wr0[ki][0] = f2tf32(Wh0[(size_t)k * HDIM + colA]);
            Wr0[ki][1] = f2tf32(Wh0[(size_t)k * HDIM + colA + 8]);
            Wr0[ki][2] = f2tf32(Wh0[(size_t)(k + 4) * HDIM + colA]);
            Wr0[ki][3] = f2tf32(Wh0[(size_t)(k + 4) * HDIM + colA + 8]);
            Wr1[ki][0] = f2tf32(Wh1[(size_t)k * HDIM + colA]);
            Wr1[ki][1] = f2tf32(Wh1[(size_t)k * HDIM + colA + 8]);
            Wr1[ki][2] = f2tf32(Wh1[(size_t)(k + 4) * HDIM + colA]);
            Wr1[ki][3] = f2tf32(Wh1[(size_t)(k + 4) * HDIM + colA + 8]);
        }
    }

    // cell thread mapping: owns c[bt*16+eb][jt*16+ej]
    const int eb = tid >> 4;
    const int ej = tid & 15;
    float c_val = 0.f;

    // position of h[eb][ej] within CTA's contiguous 1KB B-frag block
    const int lidx = ((ej >> 3) << 7) + (((eb & 7) << 2) + (ej & 3)) * 4
                     + ((eb >> 3) << 1) + ((ej >> 2) & 1);

    // Xg prefetch for t=0
    float xgv[4];
    {
        size_t xb = ((size_t)bt * 16 + eb) * GDIM + jt * 16 + ej;
        #pragma unroll
        for (int g = 0; g < 4; g++) xgv[g] = g_Xg[xb + g * HDIM];
    }
    __syncthreads();

    #pragma unroll 1
    for (int t = 0; t < T_STEPS; t++) {
        // ---- recurrent mma: pipelined LDG (distance 8) + register W ----
        float A00[4] = {0.f,0.f,0.f,0.f}, A01[4] = {0.f,0.f,0.f,0.f};
        float A10[4] = {0.f,0.f,0.f,0.f}, A11[4] = {0.f,0.f,0.f,0.f};
        if (t > 0) {
            const uint4* hp = reinterpret_cast<const uint4*>(g_hfrag[(t - 1) & 1][bt])
                              + ks * 512 + lane;
            uint4 hbuf[8];
            #pragma unroll
            for (int i = 0; i < 8; i++)
                hbuf[i] = __ldcg(hp + i * 32);
            #pragma unroll
            for (int ki = 0; ki < 16; ki++) {
                uint4 hb = hbuf[ki & 7];
                if (ki < 8)
                    hbuf[ki & 7] = __ldcg(hp + (ki + 8) * 32);   // refill under mma
                mma_tf32(A00[0], A00[1], A00[2], A00[3],
                         Wr0[ki][0], Wr0[ki][1], Wr0[ki][2], Wr0[ki][3], hb.x, hb.y);
                mma_tf32(A01[0], A01[1], A01[2], A01[3],
                         Wr0[ki][0], Wr0[ki][1], Wr0[ki][2], Wr0[ki][3], hb.z, hb.w);
                mma_tf32(A10[0], A10[1], A10[2], A10[3],
                         Wr1[ki][0], Wr1[ki][1], Wr1[ki][2], Wr1[ki][3], hb.x, hb.y);
                mma_tf32(A11[0], A11[1], A11[2], A11[3],
                         Wr1[ki][0], Wr1[ki][1], Wr1[ki][2], Wr1[ki][3], hb.z, hb.w);
            }
        }

        // ---- K-partials to smem: [ks][gatecol][batch] ----
        {
            const int r  = lane >> 2;
            const int c2 = (lane & 3) * 2;
            float* g0 = gs2 + (ks * 64 + mt * 32) * 18;        // tile 0 cols
            float* g1 = g0 + 16 * 18;                          // tile 1 cols
            *reinterpret_cast<float2*>(&g0[r * 18 + c2])           = make_float2(A00[0], A00[1]);
            *reinterpret_cast<float2*>(&g0[(r + 8) * 18 + c2])     = make_float2(A00[2], A00[3]);
            *reinterpret_cast<float2*>(&g0[r * 18 + 8 + c2])       = make_float2(A01[0], A01[1]);
            *reinterpret_cast<float2*>(&g0[(r + 8) * 18 + 8 + c2]) = make_float2(A01[2], A01[3]);
            *reinterpret_cast<float2*>(&g1[r * 18 + c2])           = make_float2(A10[0], A10[1]);
            *reinterpret_cast<float2*>(&g1[(r + 8) * 18 + c2])     = make_float2(A10[2], A10[3]);
            *reinterpret_cast<float2*>(&g1[r * 18 + 8 + c2])       = make_float2(A11[0], A11[1]);
            *reinterpret_cast<float2*>(&g1[(r + 8) * 18 + 8 + c2]) = make_float2(A11[2], A11[3]);
        }
        __syncthreads();

        // ---- cell: reduce 4 K-partials per gate + LSTM nonlinearity ----
        float hv;
        {
            float gate[4];
            #pragma unroll
            for (int g = 0; g < 4; g++) {
                float s = xgv[g];
                #pragma unroll
                for (int k = 0; k < 4; k++)
                    s += gs2[(k * 64 + g * 16 + ej) * 18 + eb];
                gate[g] = s;
            }
            float fg = 0.5f * tanh_f(0.5f * gate[0]) + 0.5f;
            float ig = 0.5f * tanh_f(0.5f * gate[1]) + 0.5f;
            float og = 0.5f * tanh_f(0.5f * gate[2]) + 0.5f;
            float ch = tanh_f(gate[3]);
            c_val = fg * c_val + ig * ch;
            hv = og * tanh_f(c_val);
            pub[lidx] = f2tf32(hv);
        }
        __syncthreads();     // pub ready; also protects gs2 WAR for next step

        // ---- warp0 publishes contiguous 1KB + releases flag ----
        if (warp == 0) {
            uint4* dst = reinterpret_cast<uint4*>(&g_hfrag[t & 1][bt][jt * 256]);
            const uint4* ps = reinterpret_cast<const uint4*>(pub);
            dst[lane]      = ps[lane];
            dst[lane + 32] = ps[lane + 32];
            __syncwarp();
            if (lane == 0 && t + 1 < T_STEPS) {
                st_rel(&g_flags[bt][jt][0], (unsigned)(t + 1));
            }
        }

        // ---- off-critical-path output + next-step Xg prefetch ----
        {
            size_t oidx = (size_t)t * BH + (size_t)(bt * 16 + eb) * HDIM + (size_t)jt * 16 + ej;
            out[oidx] = hv;
            if (t == T_STEPS - 1) {
                size_t tail = (size_t)T_STEPS * BH + (size_t)(bt * 16 + eb) * HDIM + (size_t)jt * 16 + ej;
                out[tail]      = hv;      // h_T
                out[tail + BH] = c_val;   // c_T
            }
            if (t + 1 < T_STEPS) {
                size_t xb = ((size_t)(t + 1) * BATCH + (size_t)bt * 16 + eb) * GDIM + jt * 16 + ej;
                #pragma unroll
                for (int g = 0; g < 4; g++) xgv[g] = g_Xg[xb + g * HDIM];
            }
        }

        // ---- group barrier (32 CTAs of this batch group), polled by warp1 ----
        if (t + 1 < T_STEPS) {
            if (warp == 1) {
                const unsigned* fp = &g_flags[bt][lane][0];
                while (ld_acq(fp) < (unsigned)(t + 1)) { }
            }
            __syncthreads();
        }
    }
}

// ===========================================================================
extern "C" void kernel_launch(void* const* d_in, const int* in_sizes, int n_in,
                              void* d_out, int out_size)
{
    const float* X   = (const float*)d_in[0];
    const float* Wxf = (const float*)d_in[1];
    const float* Whf = (const float*)d_in[2];
    const float* bf  = (const float*)d_in[3];
    const float* Wxi = (const float*)d_in[4];
    const float* Whi = (const float*)d_in[5];
    const float* bi  = (const float*)d_in[6];
    const float* Wxo = (const float*)d_in[7];
    const float* Who = (const float*)d_in[8];
    const float* bo  = (const float*)d_in[9];
    const float* Wxc = (const float*)d_in[10];
    const float* Whc = (const float*)d_in[11];
    const float* bc  = (const float*)d_in[12];
    float* out = (float*)d_out;

    cudaFuncSetAttribute(xgemm_kernel,
                         cudaFuncAttributeMaxDynamicSharedMemorySize, XG_SMEM);
    cudaFuncSetAttribute(lstm_rec_kernel,
                         cudaFuncAttributeMaxDynamicSharedMemorySize, REC_SMEM);

    dim3 grid1(GDIM / 256, (T_STEPS * BATCH) / 128);
    xgemm_kernel<<<grid1, 256, XG_SMEM>>>(X, Wxf, Wxi, Wxo, Wxc, bf, bi, bo, bc);
    lstm_rec_kernel<<<NCTA_REC, REC_THREADS, REC_SMEM>>>(out, Whf, Whi, Who, Whc);
}